// round 1
// baseline (speedup 1.0000x reference)
#include <cuda_runtime.h>

// Problem constants
#define NB    16
#define CD    256
#define HH    80
#define WW    60
#define LL    4800            // HH*WW
#define NHD   8
#define HDD   32
#define MR    (NB*LL)         // 76800 rows

#define EPI_NONE 0
#define EPI_ELU1 1
#define EPI_RELU 2

// ---------------- scratch (static device globals; no allocation) ----------------
__device__ float g_F0[(size_t)MR * CD];
__device__ float g_F1[(size_t)MR * CD];
__device__ float g_Q [(size_t)MR * CD];
__device__ float g_K [(size_t)MR * CD];
__device__ float g_V [(size_t)MR * CD];
__device__ float g_KV[NB * NHD * HDD * HDD];   // [nh][d][e]
__device__ float g_KS[NB * NHD * HDD];         // [nh][d]

// ---------------- positional encoding ----------------
// fac = (-log(1e4)/256)//2 == -1.0  =>  div[j] = exp(-2*j), channel c = 4*j + r
// r=0: sin((w+1)*div), r=1: cos((w+1)*div), r=2: sin((h+1)*div), r=3: cos((h+1)*div)
__device__ __forceinline__ float pe_val(int c, int l) {
    int j = c >> 2, r = c & 3;
    int h = l / WW, w = l % WW;
    float f = expf(-2.0f * (float)j);
    float pos = (r < 2) ? (float)(w + 1) : (float)(h + 1);
    float arg = pos * f;
    return (r & 1) ? cosf(arg) : sinf(arg);
}

// NCHW -> [N, L, C] with PE add (tiled transpose)
__global__ void build_pe_kernel(const float* __restrict__ feat, float* __restrict__ out) {
    __shared__ float tile[32][33];
    int n  = blockIdx.z;
    int c0 = blockIdx.y * 32;
    int l0 = blockIdx.x * 32;
    int tx = threadIdx.x, ty = threadIdx.y;
#pragma unroll
    for (int i = 0; i < 4; i++) {
        int c = c0 + ty + i * 8;
        int l = l0 + tx;
        tile[ty + i * 8][tx] = feat[((size_t)n * CD + c) * LL + l] + pe_val(c, l);
    }
    __syncthreads();
#pragma unroll
    for (int i = 0; i < 4; i++) {
        int l = l0 + ty + i * 8;
        int c = c0 + tx;
        out[((size_t)n * LL + l) * CD + c] = tile[tx][ty + i * 8];
    }
}

// [N, L, C] -> NCHW
__global__ void unbuild_kernel(const float* __restrict__ in, float* __restrict__ out) {
    __shared__ float tile[32][33];
    int n  = blockIdx.z;
    int c0 = blockIdx.y * 32;
    int l0 = blockIdx.x * 32;
    int tx = threadIdx.x, ty = threadIdx.y;
#pragma unroll
    for (int i = 0; i < 4; i++) {
        int l = l0 + ty + i * 8;
        int c = c0 + tx;
        tile[ty + i * 8][tx] = in[((size_t)n * LL + l) * CD + c];
    }
    __syncthreads();
#pragma unroll
    for (int i = 0; i < 4; i++) {
        int c = c0 + ty + i * 8;
        int l = l0 + tx;
        out[((size_t)n * CD + c) * LL + l] = tile[tx][ty + i * 8];
    }
}

// ---------------- SGEMM: C[M,N] = epi( [A|A2][M,Ktot] @ B[Ktot,N] ) ----------------
// Row-major everywhere. A covers k < K1 (row stride K1), A2 covers k >= K1 (row stride Ktot-K1).
// BM=BN=128, BK=8, 256 threads, 8x8 per thread.
__global__ __launch_bounds__(256) void sgemm_kernel(
    const float* __restrict__ A, const float* __restrict__ A2,
    const float* __restrict__ B, float* __restrict__ C,
    int M, int Ktot, int K1, int N, int epi)
{
    __shared__ float As[8][128];
    __shared__ float Bs[8][128];
    int tid = threadIdx.x;
    int rowBase = blockIdx.y * 128;
    int colBase = blockIdx.x * 128;
    int aRow = tid >> 1;
    int aCol = (tid & 1) << 2;
    int bRow = tid >> 5;
    int bCol = (tid & 31) << 2;
    int tr = (tid >> 4) << 3;
    int tc = (tid & 15) << 3;
    float acc[8][8];
#pragma unroll
    for (int i = 0; i < 8; i++)
#pragma unroll
        for (int j = 0; j < 8; j++) acc[i][j] = 0.0f;

    int K2 = Ktot - K1;
    for (int k0 = 0; k0 < Ktot; k0 += 8) {
        int kk = k0 + aCol;
        float4 av;
        if (kk < K1) av = *(const float4*)(A  + (size_t)(rowBase + aRow) * K1 + kk);
        else         av = *(const float4*)(A2 + (size_t)(rowBase + aRow) * K2 + (kk - K1));
        As[aCol + 0][aRow] = av.x;
        As[aCol + 1][aRow] = av.y;
        As[aCol + 2][aRow] = av.z;
        As[aCol + 3][aRow] = av.w;
        *(float4*)&Bs[bRow][bCol] =
            *(const float4*)(B + (size_t)(k0 + bRow) * N + colBase + bCol);
        __syncthreads();
#pragma unroll
        for (int k = 0; k < 8; k++) {
            float a[8], b[8];
            *(float4*)(a)     = *(float4*)&As[k][tr];
            *(float4*)(a + 4) = *(float4*)&As[k][tr + 4];
            *(float4*)(b)     = *(float4*)&Bs[k][tc];
            *(float4*)(b + 4) = *(float4*)&Bs[k][tc + 4];
#pragma unroll
            for (int i = 0; i < 8; i++)
#pragma unroll
                for (int j = 0; j < 8; j++)
                    acc[i][j] = fmaf(a[i], b[j], acc[i][j]);
        }
        __syncthreads();
    }
#pragma unroll
    for (int i = 0; i < 8; i++) {
        size_t crow = (size_t)(rowBase + tr + i) * N + colBase + tc;
#pragma unroll
        for (int j = 0; j < 8; j++) {
            float v = acc[i][j];
            if (epi == EPI_ELU1)      v = (v > 0.0f) ? (v + 1.0f) : expf(v);
            else if (epi == EPI_RELU) v = fmaxf(v, 0.0f);
            C[crow + j] = v;
        }
    }
}

// ---------------- KV = sum_s K[s,d] * v[s,e], Ksum = sum_s K[s,d] per (n,h) ----------------
#define KV_CHUNKS 20
#define KV_SC (LL / KV_CHUNKS)   // 240
__global__ void kv_reduce_kernel(const float* __restrict__ Kb, const float* __restrict__ Vb,
                                 float* __restrict__ KV, float* __restrict__ KS) {
    int nh = blockIdx.x;             // 0..127
    int n = nh >> 3, h = nh & 7;
    int t = threadIdx.x;             // 256
    int d = t & 31;
    int eg = t >> 5;                 // 0..7 (e group of 4)
    int s0 = blockIdx.y * KV_SC;
    float a0 = 0, a1 = 0, a2 = 0, a3 = 0, ks = 0;
    for (int s = s0; s < s0 + KV_SC; s++) {
        size_t base = ((size_t)(n * LL + s) * NHD + h) * HDD;
        float kd = Kb[base + d];
        float4 vv = *(const float4*)(Vb + base + eg * 4);
        a0 = fmaf(kd, vv.x, a0);
        a1 = fmaf(kd, vv.y, a1);
        a2 = fmaf(kd, vv.z, a2);
        a3 = fmaf(kd, vv.w, a3);
        ks += kd;
    }
    float* kvp = KV + ((size_t)nh * HDD + d) * HDD + eg * 4;
    atomicAdd(kvp + 0, a0);
    atomicAdd(kvp + 1, a1);
    atomicAdd(kvp + 2, a2);
    atomicAdd(kvp + 3, a3);
    if (eg == 0) atomicAdd(KS + nh * HDD + d, ks);
}

// ---------------- out[n,l,h,e] = (Q . KV[:,e]) / (Q . Ksum + eps) ----------------
#define AT_CHUNKS 40
#define AT_RPB (LL / AT_CHUNKS)      // 120 rows per block
__global__ void attn_apply_kernel(const float* __restrict__ Qb, const float* __restrict__ KV,
                                  const float* __restrict__ KS, float* __restrict__ O) {
    __shared__ float kvs[32][33];
    __shared__ float kss[32];
    int n = blockIdx.z, h = blockIdx.y;
    int nh = n * NHD + h;
    int t = threadIdx.x, lane = t & 31, w = t >> 5;
    for (int i = t; i < 1024; i += 256) kvs[i >> 5][i & 31] = KV[(size_t)nh * 1024 + i];
    if (t < 32) kss[t] = KS[nh * 32 + t];
    __syncthreads();
    int l0 = blockIdx.x * AT_RPB + w * (AT_RPB / 8);
    for (int r = 0; r < AT_RPB / 8; r++) {
        int l = l0 + r;
        size_t base = ((size_t)(n * LL + l) * NHD + h) * HDD;
        float qd = Qb[base + lane];
        float zs = qd * kss[lane];
#pragma unroll
        for (int o = 16; o; o >>= 1) zs += __shfl_xor_sync(0xffffffffu, zs, o);
        float z = 1.0f / (zs + 1e-6f);
        float acc = 0.0f;
#pragma unroll
        for (int d = 0; d < 32; d++) {
            float qv = __shfl_sync(0xffffffffu, qd, d);
            acc = fmaf(qv, kvs[d][lane], acc);
        }
        O[base + lane] = acc * z;
    }
}

// ---------------- LayerNorm over last dim 256, 1 warp/row ----------------
__global__ void layernorm_kernel(float* __restrict__ X,
                                 const float* __restrict__ g, const float* __restrict__ b) {
    int row = blockIdx.x * 8 + (threadIdx.x >> 5);
    int lane = threadIdx.x & 31;
    size_t base = (size_t)row * CD;
    float v[8];
    float s = 0.0f;
#pragma unroll
    for (int i = 0; i < 8; i++) { v[i] = X[base + i * 32 + lane]; s += v[i]; }
#pragma unroll
    for (int o = 16; o; o >>= 1) s += __shfl_xor_sync(0xffffffffu, s, o);
    float mu = s * (1.0f / 256.0f);
    float q = 0.0f;
#pragma unroll
    for (int i = 0; i < 8; i++) { float d = v[i] - mu; q = fmaf(d, d, q); }
#pragma unroll
    for (int o = 16; o; o >>= 1) q += __shfl_xor_sync(0xffffffffu, q, o);
    float rs = rsqrtf(q * (1.0f / 256.0f) + 1e-5f);
#pragma unroll
    for (int i = 0; i < 8; i++)
        X[base + i * 32 + lane] = (v[i] - mu) * rs * g[i * 32 + lane] + b[i * 32 + lane];
}

// X += LayerNorm(Y)
__global__ void ln_residual_kernel(float* __restrict__ X, const float* __restrict__ Y,
                                   const float* __restrict__ g, const float* __restrict__ b) {
    int row = blockIdx.x * 8 + (threadIdx.x >> 5);
    int lane = threadIdx.x & 31;
    size_t base = (size_t)row * CD;
    float v[8];
    float s = 0.0f;
#pragma unroll
    for (int i = 0; i < 8; i++) { v[i] = Y[base + i * 32 + lane]; s += v[i]; }
#pragma unroll
    for (int o = 16; o; o >>= 1) s += __shfl_xor_sync(0xffffffffu, s, o);
    float mu = s * (1.0f / 256.0f);
    float q = 0.0f;
#pragma unroll
    for (int i = 0; i < 8; i++) { float d = v[i] - mu; q = fmaf(d, d, q); }
#pragma unroll
    for (int o = 16; o; o >>= 1) q += __shfl_xor_sync(0xffffffffu, q, o);
    float rs = rsqrtf(q * (1.0f / 256.0f) + 1e-5f);
#pragma unroll
    for (int i = 0; i < 8; i++)
        X[base + i * 32 + lane] += (v[i] - mu) * rs * g[i * 32 + lane] + b[i * 32 + lane];
}

// ---------------- launch ----------------
extern "C" void kernel_launch(void* const* d_in, const int* in_sizes, int n_in,
                              void* d_out, int out_size) {
    const float* feat0 = (const float*)d_in[0];
    const float* feat1 = (const float*)d_in[1];
    const float* Wq = (const float*)d_in[2];
    const float* Wk = (const float*)d_in[3];
    const float* Wv = (const float*)d_in[4];
    const float* Wm = (const float*)d_in[5];
    const float* W1 = (const float*)d_in[6];
    const float* W2 = (const float*)d_in[7];
    const float* g1 = (const float*)d_in[8];
    const float* b1 = (const float*)d_in[9];
    const float* g2 = (const float*)d_in[10];
    const float* b2 = (const float*)d_in[11];

    float *F0, *F1, *Qb, *Kb, *Vb, *KV, *KS;
    cudaGetSymbolAddress((void**)&F0, g_F0);
    cudaGetSymbolAddress((void**)&F1, g_F1);
    cudaGetSymbolAddress((void**)&Qb, g_Q);
    cudaGetSymbolAddress((void**)&Kb, g_K);
    cudaGetSymbolAddress((void**)&Vb, g_V);
    cudaGetSymbolAddress((void**)&KV, g_KV);
    cudaGetSymbolAddress((void**)&KS, g_KS);

    dim3 tb(32, 8);
    dim3 tg(LL / 32, CD / 32, NB);
    build_pe_kernel<<<tg, tb>>>(feat0, F0);
    build_pe_kernel<<<tg, tb>>>(feat1, F1);

    dim3 gg(CD / 128, MR / 128);   // (2, 600)

    for (int i = 0; i < 2; i++) {
        const float* wq = Wq + (size_t)i * CD * CD;
        const float* wk = Wk + (size_t)i * CD * CD;
        const float* wv = Wv + (size_t)i * CD * CD;
        const float* wm = Wm + (size_t)i * CD * CD;
        const float* w1 = W1 + (size_t)i * 2 * CD * CD;
        const float* w2 = W2 + (size_t)i * CD * CD;

        // projections (elu+1 fused into q,k)
        sgemm_kernel<<<gg, 256>>>(F0, F0, wq, Qb, MR, CD, CD, CD, EPI_ELU1);
        sgemm_kernel<<<gg, 256>>>(F1, F1, wk, Kb, MR, CD, CD, CD, EPI_ELU1);
        sgemm_kernel<<<gg, 256>>>(F1, F1, wv, Vb, MR, CD, CD, CD, EPI_NONE);

        // KV / Ksum reduction
        cudaMemsetAsync(KV, 0, sizeof(float) * NB * NHD * HDD * HDD, 0);
        cudaMemsetAsync(KS, 0, sizeof(float) * NB * NHD * HDD, 0);
        kv_reduce_kernel<<<dim3(NB * NHD, KV_CHUNKS), 256>>>(Kb, Vb, KV, KS);

        // attention apply -> reuse Kb as output
        attn_apply_kernel<<<dim3(AT_CHUNKS, NHD, NB), 256>>>(Qb, KV, KS, Kb);

        // merge projection -> Vb, then LN1 in place
        sgemm_kernel<<<gg, 256>>>(Kb, Kb, wm, Vb, MR, CD, CD, CD, EPI_NONE);
        layernorm_kernel<<<MR / 8, 256>>>(Vb, g1 + i * CD, b1 + i * CD);

        // FFN: relu([x|msg] @ W1) -> Qb; @ W2 -> Kb; x += LN2(Kb)
        sgemm_kernel<<<gg, 256>>>(F0, Vb, w1, Qb, MR, 2 * CD, CD, CD, EPI_RELU);
        sgemm_kernel<<<gg, 256>>>(Qb, Qb, w2, Kb, MR, CD, CD, CD, EPI_NONE);
        ln_residual_kernel<<<MR / 8, 256>>>(F0, Kb, g2 + i * CD, b2 + i * CD);
    }

    unbuild_kernel<<<tg, tb>>>(F0, (float*)d_out);
}

// round 2
// speedup vs baseline: 3.9220x; 3.9220x over previous
#include <cuda_runtime.h>
#include <cstdint>

// Problem constants
#define NB    16
#define CD    256
#define HH    80
#define WW    60
#define LL    4800            // HH*WW
#define NHD   8
#define HDD   32
#define MR    (NB*LL)         // 76800 rows

#define EPI_NONE 0
#define EPI_ELU1 1
#define EPI_RELU 2

// ---------------- scratch (static device globals; no allocation) ----------------
__device__ float g_F0[(size_t)MR * CD];
__device__ float g_F1[(size_t)MR * CD];
__device__ float g_Q [(size_t)MR * CD];
__device__ float g_K [(size_t)MR * CD];
__device__ float g_V [(size_t)MR * CD];
__device__ float g_PE[(size_t)CD * LL];
__device__ float g_KV[NB * NHD * HDD * HDD];   // [nh][d][e]
__device__ float g_KS[NB * NHD * HDD];         // [nh][d]

// ---------------- positional encoding ----------------
// fac = (-log(1e4)/256)//2 == -1.0  =>  div[j] = exp(-2*j), channel c = 4*j + r
__global__ void pe_precompute_kernel(float* __restrict__ PE) {
    int idx = blockIdx.x * blockDim.x + threadIdx.x;
    if (idx >= CD * LL) return;
    int c = idx / LL, l = idx % LL;
    int j = c >> 2, r = c & 3;
    int h = l / WW, w = l % WW;
    float f = expf(-2.0f * (float)j);
    float pos = (r < 2) ? (float)(w + 1) : (float)(h + 1);
    float arg = pos * f;
    PE[idx] = (r & 1) ? cosf(arg) : sinf(arg);
}

// NCHW -> [N, L, C] with PE add (tiled transpose)
__global__ void build_pe_kernel(const float* __restrict__ feat, const float* __restrict__ PE,
                                float* __restrict__ out) {
    __shared__ float tile[32][33];
    int n  = blockIdx.z;
    int c0 = blockIdx.y * 32;
    int l0 = blockIdx.x * 32;
    int tx = threadIdx.x, ty = threadIdx.y;
#pragma unroll
    for (int i = 0; i < 4; i++) {
        int c = c0 + ty + i * 8;
        int l = l0 + tx;
        tile[ty + i * 8][tx] = feat[((size_t)n * CD + c) * LL + l] + PE[(size_t)c * LL + l];
    }
    __syncthreads();
#pragma unroll
    for (int i = 0; i < 4; i++) {
        int l = l0 + ty + i * 8;
        int c = c0 + tx;
        out[((size_t)n * LL + l) * CD + c] = tile[tx][ty + i * 8];
    }
}

// [N, L, C] -> NCHW
__global__ void unbuild_kernel(const float* __restrict__ in, float* __restrict__ out) {
    __shared__ float tile[32][33];
    int n  = blockIdx.z;
    int c0 = blockIdx.y * 32;
    int l0 = blockIdx.x * 32;
    int tx = threadIdx.x, ty = threadIdx.y;
#pragma unroll
    for (int i = 0; i < 4; i++) {
        int l = l0 + ty + i * 8;
        int c = c0 + tx;
        tile[ty + i * 8][tx] = in[((size_t)n * LL + l) * CD + c];
    }
    __syncthreads();
#pragma unroll
    for (int i = 0; i < 4; i++) {
        int c = c0 + ty + i * 8;
        int l = l0 + tx;
        out[((size_t)n * CD + c) * LL + l] = tile[tx][ty + i * 8];
    }
}

// ---------------- TF32 tensor-core GEMM ----------------
// C[M,N] = epi( [A|A2][M,Ktot] @ B[Ktot,N] ), all row-major fp32.
// BM=128, BN=128, BK=16, 256 threads (8 warps), warp tile 32x64 via m16n8k8 TF32.
#define BK 16
#define APAD 20    // As row stride (floats): conflict-free for frag loads
#define BPAD 136   // Bs row stride (floats): conflict-free for frag loads

__device__ __forceinline__ void cp16(void* dst, const void* src) {
    uint32_t d = (uint32_t)__cvta_generic_to_shared(dst);
    asm volatile("cp.async.cg.shared.global [%0], [%1], 16;\n" :: "r"(d), "l"(src));
}
__device__ __forceinline__ uint32_t f2tf(float x) {
    uint32_t u;
    asm("cvt.rna.tf32.f32 %0, %1;" : "=r"(u) : "f"(x));
    return u;
}

__global__ __launch_bounds__(256, 2) void tgemm_kernel(
    const float* __restrict__ A, const float* __restrict__ A2,
    const float* __restrict__ B, float* __restrict__ C,
    int M, int Ktot, int K1, int N, int epi)
{
    __shared__ float As[2][128][APAD];
    __shared__ float Bs[2][BK][BPAD];

    int tid = threadIdx.x;
    int warp = tid >> 5;
    int lane = tid & 31;
    int g = lane >> 2;     // group 0..7
    int q = lane & 3;      // quad  0..3
    int rowBase = blockIdx.y * 128;
    int colBase = blockIdx.x * 128;
    int wm0 = (warp >> 1) * 32;   // warp M offset (4 warps in M)
    int wn0 = (warp & 1) * 64;    // warp N offset (2 warps in N)
    int K2 = Ktot - K1;

    float acc[2][8][4];
#pragma unroll
    for (int mt = 0; mt < 2; mt++)
#pragma unroll
        for (int nt = 0; nt < 8; nt++)
#pragma unroll
            for (int r = 0; r < 4; r++) acc[mt][nt][r] = 0.0f;

    // A chunk mapping: chunks c = tid, tid+256 ; row = c>>2, colc = c&3 (4 floats each)
    int aRow0 = tid >> 2,           aColc0 = tid & 3;
    int aRow1 = (tid + 256) >> 2,   aColc1 = (tid + 256) & 3;
    // B chunk mapping: row = c>>5 (0..15), col = (c&31)*4
    int bRow0 = tid >> 5,           bCol0 = (tid & 31) << 2;
    int bRow1 = (tid + 256) >> 5,   bCol1 = bCol0;

    int NT = Ktot / BK;

    auto issue = [&](int kt, int buf) {
        int k0 = kt * BK;
        // A chunks
        {
            int kk = k0 + aColc0 * 4;
            const float* src = (kk < K1) ? (A  + (size_t)(rowBase + aRow0) * K1 + kk)
                                         : (A2 + (size_t)(rowBase + aRow0) * K2 + (kk - K1));
            cp16(&As[buf][aRow0][aColc0 * 4], src);
        }
        {
            int kk = k0 + aColc1 * 4;
            const float* src = (kk < K1) ? (A  + (size_t)(rowBase + aRow1) * K1 + kk)
                                         : (A2 + (size_t)(rowBase + aRow1) * K2 + (kk - K1));
            cp16(&As[buf][aRow1][aColc1 * 4], src);
        }
        // B chunks
        cp16(&Bs[buf][bRow0][bCol0], B + (size_t)(k0 + bRow0) * N + colBase + bCol0);
        cp16(&Bs[buf][bRow1][bCol1], B + (size_t)(k0 + bRow1) * N + colBase + bCol1);
    };

    issue(0, 0);
    asm volatile("cp.async.commit_group;\n");

    int buf = 0;
    for (int kt = 0; kt < NT; kt++) {
        if (kt + 1 < NT) {
            issue(kt + 1, buf ^ 1);
            asm volatile("cp.async.commit_group;\n");
            asm volatile("cp.async.wait_group 1;\n");
        } else {
            asm volatile("cp.async.wait_group 0;\n");
        }
        __syncthreads();

#pragma unroll
        for (int ks = 0; ks < 2; ks++) {
            int kb = ks * 8;
            uint32_t af[2][4];
#pragma unroll
            for (int mt = 0; mt < 2; mt++) {
                int m = wm0 + mt * 16;
                af[mt][0] = f2tf(As[buf][m + g    ][kb + q    ]);
                af[mt][1] = f2tf(As[buf][m + g + 8][kb + q    ]);
                af[mt][2] = f2tf(As[buf][m + g    ][kb + q + 4]);
                af[mt][3] = f2tf(As[buf][m + g + 8][kb + q + 4]);
            }
            uint32_t bf[8][2];
#pragma unroll
            for (int nt = 0; nt < 8; nt++) {
                int n = wn0 + nt * 8 + g;
                bf[nt][0] = f2tf(Bs[buf][kb + q    ][n]);
                bf[nt][1] = f2tf(Bs[buf][kb + q + 4][n]);
            }
#pragma unroll
            for (int mt = 0; mt < 2; mt++)
#pragma unroll
                for (int nt = 0; nt < 8; nt++) {
                    asm volatile(
                        "mma.sync.aligned.m16n8k8.row.col.f32.tf32.tf32.f32 "
                        "{%0,%1,%2,%3}, {%4,%5,%6,%7}, {%8,%9}, {%0,%1,%2,%3};\n"
                        : "+f"(acc[mt][nt][0]), "+f"(acc[mt][nt][1]),
                          "+f"(acc[mt][nt][2]), "+f"(acc[mt][nt][3])
                        : "r"(af[mt][0]), "r"(af[mt][1]), "r"(af[mt][2]), "r"(af[mt][3]),
                          "r"(bf[nt][0]), "r"(bf[nt][1]));
                }
        }
        buf ^= 1;
        __syncthreads();
    }

    // epilogue: c0,c1 -> (row g, col 2q), c2,c3 -> (row g+8, col 2q)
#pragma unroll
    for (int mt = 0; mt < 2; mt++) {
        int row = rowBase + wm0 + mt * 16 + g;
#pragma unroll
        for (int nt = 0; nt < 8; nt++) {
            int col = colBase + wn0 + nt * 8 + 2 * q;
            float v0 = acc[mt][nt][0], v1 = acc[mt][nt][1];
            float v2 = acc[mt][nt][2], v3 = acc[mt][nt][3];
            if (epi == EPI_ELU1) {
                v0 = (v0 > 0.f) ? v0 + 1.f : expf(v0);
                v1 = (v1 > 0.f) ? v1 + 1.f : expf(v1);
                v2 = (v2 > 0.f) ? v2 + 1.f : expf(v2);
                v3 = (v3 > 0.f) ? v3 + 1.f : expf(v3);
            } else if (epi == EPI_RELU) {
                v0 = fmaxf(v0, 0.f); v1 = fmaxf(v1, 0.f);
                v2 = fmaxf(v2, 0.f); v3 = fmaxf(v3, 0.f);
            }
            *(float2*)(C + (size_t)row * N + col)       = make_float2(v0, v1);
            *(float2*)(C + (size_t)(row + 8) * N + col) = make_float2(v2, v3);
        }
    }
}

// ---------------- KV = sum_s K[s,d] * v[s,e], Ksum = sum_s K[s,d] per (n,h) ----------------
#define KV_CHUNKS 20
#define KV_SC (LL / KV_CHUNKS)   // 240
__global__ void kv_reduce_kernel(const float* __restrict__ Kb, const float* __restrict__ Vb,
                                 float* __restrict__ KV, float* __restrict__ KS) {
    int nh = blockIdx.x;             // 0..127
    int n = nh >> 3, h = nh & 7;
    int t = threadIdx.x;             // 256
    int d = t & 31;
    int eg = t >> 5;                 // 0..7 (e group of 4)
    int s0 = blockIdx.y * KV_SC;
    float a0 = 0, a1 = 0, a2 = 0, a3 = 0, ks = 0;
    for (int s = s0; s < s0 + KV_SC; s++) {
        size_t base = ((size_t)(n * LL + s) * NHD + h) * HDD;
        float kd = Kb[base + d];
        float4 vv = *(const float4*)(Vb + base + eg * 4);
        a0 = fmaf(kd, vv.x, a0);
        a1 = fmaf(kd, vv.y, a1);
        a2 = fmaf(kd, vv.z, a2);
        a3 = fmaf(kd, vv.w, a3);
        ks += kd;
    }
    float* kvp = KV + ((size_t)nh * HDD + d) * HDD + eg * 4;
    atomicAdd(kvp + 0, a0);
    atomicAdd(kvp + 1, a1);
    atomicAdd(kvp + 2, a2);
    atomicAdd(kvp + 3, a3);
    if (eg == 0) atomicAdd(KS + nh * HDD + d, ks);
}

// ---------------- out[n,l,h,e] = (Q . KV[:,e]) / (Q . Ksum + eps) ----------------
#define AT_CHUNKS 40
#define AT_RPB (LL / AT_CHUNKS)      // 120 rows per block
__global__ void attn_apply_kernel(const float* __restrict__ Qb, const float* __restrict__ KV,
                                  const float* __restrict__ KS, float* __restrict__ O) {
    __shared__ float kvs[32][33];
    __shared__ float kss[32];
    int n = blockIdx.z, h = blockIdx.y;
    int nh = n * NHD + h;
    int t = threadIdx.x, lane = t & 31, w = t >> 5;
    for (int i = t; i < 1024; i += 256) kvs[i >> 5][i & 31] = KV[(size_t)nh * 1024 + i];
    if (t < 32) kss[t] = KS[nh * 32 + t];
    __syncthreads();
    int l0 = blockIdx.x * AT_RPB + w * (AT_RPB / 8);
    for (int r = 0; r < AT_RPB / 8; r++) {
        int l = l0 + r;
        size_t base = ((size_t)(n * LL + l) * NHD + h) * HDD;
        float qd = Qb[base + lane];
        float zs = qd * kss[lane];
#pragma unroll
        for (int o = 16; o; o >>= 1) zs += __shfl_xor_sync(0xffffffffu, zs, o);
        float z = 1.0f / (zs + 1e-6f);
        float acc = 0.0f;
#pragma unroll
        for (int d = 0; d < 32; d++) {
            float qv = __shfl_sync(0xffffffffu, qd, d);
            acc = fmaf(qv, kvs[d][lane], acc);
        }
        O[base + lane] = acc * z;
    }
}

// ---------------- LayerNorm over last dim 256, 1 warp/row ----------------
__global__ void layernorm_kernel(float* __restrict__ X,
                                 const float* __restrict__ g, const float* __restrict__ b) {
    int row = blockIdx.x * 8 + (threadIdx.x >> 5);
    int lane = threadIdx.x & 31;
    size_t base = (size_t)row * CD;
    float v[8];
    float s = 0.0f;
#pragma unroll
    for (int i = 0; i < 8; i++) { v[i] = X[base + i * 32 + lane]; s += v[i]; }
#pragma unroll
    for (int o = 16; o; o >>= 1) s += __shfl_xor_sync(0xffffffffu, s, o);
    float mu = s * (1.0f / 256.0f);
    float q = 0.0f;
#pragma unroll
    for (int i = 0; i < 8; i++) { float d = v[i] - mu; q = fmaf(d, d, q); }
#pragma unroll
    for (int o = 16; o; o >>= 1) q += __shfl_xor_sync(0xffffffffu, q, o);
    float rs = rsqrtf(q * (1.0f / 256.0f) + 1e-5f);
#pragma unroll
    for (int i = 0; i < 8; i++)
        X[base + i * 32 + lane] = (v[i] - mu) * rs * g[i * 32 + lane] + b[i * 32 + lane];
}

// X += LayerNorm(Y)
__global__ void ln_residual_kernel(float* __restrict__ X, const float* __restrict__ Y,
                                   const float* __restrict__ g, const float* __restrict__ b) {
    int row = blockIdx.x * 8 + (threadIdx.x >> 5);
    int lane = threadIdx.x & 31;
    size_t base = (size_t)row * CD;
    float v[8];
    float s = 0.0f;
#pragma unroll
    for (int i = 0; i < 8; i++) { v[i] = Y[base + i * 32 + lane]; s += v[i]; }
#pragma unroll
    for (int o = 16; o; o >>= 1) s += __shfl_xor_sync(0xffffffffu, s, o);
    float mu = s * (1.0f / 256.0f);
    float q = 0.0f;
#pragma unroll
    for (int i = 0; i < 8; i++) { float d = v[i] - mu; q = fmaf(d, d, q); }
#pragma unroll
    for (int o = 16; o; o >>= 1) q += __shfl_xor_sync(0xffffffffu, q, o);
    float rs = rsqrtf(q * (1.0f / 256.0f) + 1e-5f);
#pragma unroll
    for (int i = 0; i < 8; i++)
        X[base + i * 32 + lane] += (v[i] - mu) * rs * g[i * 32 + lane] + b[i * 32 + lane];
}

// ---------------- launch ----------------
extern "C" void kernel_launch(void* const* d_in, const int* in_sizes, int n_in,
                              void* d_out, int out_size) {
    const float* feat0 = (const float*)d_in[0];
    const float* feat1 = (const float*)d_in[1];
    const float* Wq = (const float*)d_in[2];
    const float* Wk = (const float*)d_in[3];
    const float* Wv = (const float*)d_in[4];
    const float* Wm = (const float*)d_in[5];
    const float* W1 = (const float*)d_in[6];
    const float* W2 = (const float*)d_in[7];
    const float* g1 = (const float*)d_in[8];
    const float* b1 = (const float*)d_in[9];
    const float* g2 = (const float*)d_in[10];
    const float* b2 = (const float*)d_in[11];

    float *F0, *F1, *Qb, *Kb, *Vb, *KV, *KS, *PE;
    cudaGetSymbolAddress((void**)&F0, g_F0);
    cudaGetSymbolAddress((void**)&F1, g_F1);
    cudaGetSymbolAddress((void**)&Qb, g_Q);
    cudaGetSymbolAddress((void**)&Kb, g_K);
    cudaGetSymbolAddress((void**)&Vb, g_V);
    cudaGetSymbolAddress((void**)&KV, g_KV);
    cudaGetSymbolAddress((void**)&KS, g_KS);
    cudaGetSymbolAddress((void**)&PE, g_PE);

    pe_precompute_kernel<<<(CD * LL + 255) / 256, 256>>>(PE);

    dim3 tb(32, 8);
    dim3 tg(LL / 32, CD / 32, NB);
    build_pe_kernel<<<tg, tb>>>(feat0, PE, F0);
    build_pe_kernel<<<tg, tb>>>(feat1, PE, F1);

    dim3 gg(CD / 128, MR / 128);   // (2, 600)

    for (int i = 0; i < 2; i++) {
        const float* wq = Wq + (size_t)i * CD * CD;
        const float* wk = Wk + (size_t)i * CD * CD;
        const float* wv = Wv + (size_t)i * CD * CD;
        const float* wm = Wm + (size_t)i * CD * CD;
        const float* w1 = W1 + (size_t)i * 2 * CD * CD;
        const float* w2 = W2 + (size_t)i * CD * CD;

        // projections (elu+1 fused into q,k)
        tgemm_kernel<<<gg, 256>>>(F0, F0, wq, Qb, MR, CD, CD, CD, EPI_ELU1);
        tgemm_kernel<<<gg, 256>>>(F1, F1, wk, Kb, MR, CD, CD, CD, EPI_ELU1);
        tgemm_kernel<<<gg, 256>>>(F1, F1, wv, Vb, MR, CD, CD, CD, EPI_NONE);

        // KV / Ksum reduction
        cudaMemsetAsync(KV, 0, sizeof(float) * NB * NHD * HDD * HDD, 0);
        cudaMemsetAsync(KS, 0, sizeof(float) * NB * NHD * HDD, 0);
        kv_reduce_kernel<<<dim3(NB * NHD, KV_CHUNKS), 256>>>(Kb, Vb, KV, KS);

        // attention apply -> reuse Kb as output
        attn_apply_kernel<<<dim3(AT_CHUNKS, NHD, NB), 256>>>(Qb, KV, KS, Kb);

        // merge projection -> Vb, then LN1 in place
        tgemm_kernel<<<gg, 256>>>(Kb, Kb, wm, Vb, MR, CD, CD, CD, EPI_NONE);
        layernorm_kernel<<<MR / 8, 256>>>(Vb, g1 + i * CD, b1 + i * CD);

        // FFN: relu([x|msg] @ W1) -> Qb; @ W2 -> Kb; x += LN2(Kb)
        tgemm_kernel<<<gg, 256>>>(F0, Vb, w1, Qb, MR, 2 * CD, CD, CD, EPI_RELU);
        tgemm_kernel<<<gg, 256>>>(Qb, Qb, w2, Kb, MR, CD, CD, CD, EPI_NONE);
        ln_residual_kernel<<<MR / 8, 256>>>(F0, Kb, g2 + i * CD, b2 + i * CD);
    }

    unbuild_kernel<<<tg, tb>>>(F0, (float*)d_out);
}

// round 3
// speedup vs baseline: 3.9565x; 1.0088x over previous
#include <cuda_runtime.h>
#include <cstdint>

// Problem constants
#define NB    16
#define CD    256
#define HH    80
#define WW    60
#define LL    4800            // HH*WW
#define NHD   8
#define HDD   32
#define MR    (NB*LL)         // 76800 rows

#define EPI_NONE     0
#define EPI_ELU1     1
#define EPI_RELU_RND 2

// ---------------- scratch (static device globals; no allocation) ----------------
__device__ float g_F0 [(size_t)MR * CD];   // exact x (residual/output)
__device__ float g_F0r[(size_t)MR * CD];   // tf32-rounded shadow of F0 (GEMM A)
__device__ float g_F1 [(size_t)MR * CD];   // tf32-rounded (GEMM-only consumer)
__device__ float g_Q  [(size_t)MR * CD];
__device__ float g_K  [(size_t)MR * CD];
__device__ float g_V  [(size_t)MR * CD];
__device__ float g_PE [(size_t)CD * LL];
__device__ float g_KV [NB * NHD * HDD * HDD];
__device__ float g_KS [NB * NHD * HDD];
// rounded weights (both layers)
__device__ float g_Wq[2 * CD * CD];
__device__ float g_Wk[2 * CD * CD];
__device__ float g_Wv[2 * CD * CD];
__device__ float g_Wm[2 * CD * CD];
__device__ float g_W1[2 * 2 * CD * CD];
__device__ float g_W2[2 * CD * CD];

__device__ __forceinline__ float rnd_tf32(float x) {
    float r;
    asm("cvt.rna.tf32.f32 %0, %1;" : "=f"(r) : "f"(x));
    return r;
}

// ---------------- weight prep: round all weights to tf32 once ----------------
__global__ void weight_prep_kernel(
    const float* __restrict__ wq, const float* __restrict__ wk,
    const float* __restrict__ wv, const float* __restrict__ wm,
    const float* __restrict__ w1, const float* __restrict__ w2)
{
    int i = blockIdx.x * blockDim.x + threadIdx.x;
    const int S = 2 * CD * CD;          // 131072
    if (i < S) g_Wq[i] = rnd_tf32(wq[i]);
    if (i < S) g_Wk[i] = rnd_tf32(wk[i]);
    if (i < S) g_Wv[i] = rnd_tf32(wv[i]);
    if (i < S) g_Wm[i] = rnd_tf32(wm[i]);
    if (i < S) g_W2[i] = rnd_tf32(w2[i]);
    if (i < 2 * S) g_W1[i] = rnd_tf32(w1[i]);
}

// ---------------- positional encoding ----------------
// fac = (-log(1e4)/256)//2 == -1.0  =>  div[j] = exp(-2*j)
__global__ void pe_precompute_kernel(float* __restrict__ PE) {
    int idx = blockIdx.x * blockDim.x + threadIdx.x;
    if (idx >= CD * LL) return;
    int c = idx / LL, l = idx % LL;
    int j = c >> 2, r = c & 3;
    int h = l / WW, w = l % WW;
    float f = expf(-2.0f * (float)j);
    float pos = (r < 2) ? (float)(w + 1) : (float)(h + 1);
    float arg = pos * f;
    PE[idx] = (r & 1) ? cosf(arg) : sinf(arg);
}

// NCHW -> [N,L,C] with PE add. Writes exact to out, optionally tf32-rounded to outR.
__global__ void build_pe_kernel(const float* __restrict__ feat, const float* __restrict__ PE,
                                float* __restrict__ out, float* __restrict__ outR) {
    __shared__ float tile[32][33];
    int n  = blockIdx.z;
    int c0 = blockIdx.y * 32;
    int l0 = blockIdx.x * 32;
    int tx = threadIdx.x, ty = threadIdx.y;
#pragma unroll
    for (int i = 0; i < 4; i++) {
        int c = c0 + ty + i * 8;
        int l = l0 + tx;
        tile[ty + i * 8][tx] = feat[((size_t)n * CD + c) * LL + l] + PE[(size_t)c * LL + l];
    }
    __syncthreads();
#pragma unroll
    for (int i = 0; i < 4; i++) {
        int l = l0 + ty + i * 8;
        int c = c0 + tx;
        float v = tile[tx][ty + i * 8];
        size_t o = ((size_t)n * LL + l) * CD + c;
        if (out)  out[o]  = v;
        if (outR) outR[o] = rnd_tf32(v);
    }
}

// [N,L,C] -> NCHW
__global__ void unbuild_kernel(const float* __restrict__ in, float* __restrict__ out) {
    __shared__ float tile[32][33];
    int n  = blockIdx.z;
    int c0 = blockIdx.y * 32;
    int l0 = blockIdx.x * 32;
    int tx = threadIdx.x, ty = threadIdx.y;
#pragma unroll
    for (int i = 0; i < 4; i++) {
        int l = l0 + ty + i * 8;
        int c = c0 + tx;
        tile[ty + i * 8][tx] = in[((size_t)n * LL + l) * CD + c];
    }
    __syncthreads();
#pragma unroll
    for (int i = 0; i < 4; i++) {
        int c = c0 + ty + i * 8;
        int l = l0 + tx;
        out[((size_t)n * CD + c) * LL + l] = tile[tx][ty + i * 8];
    }
}

// ---------------- TF32 tensor-core GEMM (inputs pre-rounded; no cvt in loop) ----------------
#define BK 16
#define APAD 20
#define BPAD 136

__device__ __forceinline__ void cp16(void* dst, const void* src) {
    uint32_t d = (uint32_t)__cvta_generic_to_shared(dst);
    asm volatile("cp.async.cg.shared.global [%0], [%1], 16;\n" :: "r"(d), "l"(src));
}

__global__ __launch_bounds__(256, 2) void tgemm_kernel(
    const float* __restrict__ A, const float* __restrict__ A2,
    const float* __restrict__ B, float* __restrict__ C,
    int M, int Ktot, int K1, int N, int epi)
{
    __shared__ float As[2][128][APAD];
    __shared__ float Bs[2][BK][BPAD];

    int tid = threadIdx.x;
    int warp = tid >> 5;
    int lane = tid & 31;
    int g = lane >> 2;
    int q = lane & 3;
    int rowBase = blockIdx.y * 128;
    int colBase = blockIdx.x * 128;
    int wm0 = (warp >> 1) * 32;
    int wn0 = (warp & 1) * 64;
    int K2 = Ktot - K1;

    float acc[2][8][4];
#pragma unroll
    for (int mt = 0; mt < 2; mt++)
#pragma unroll
        for (int nt = 0; nt < 8; nt++)
#pragma unroll
            for (int r = 0; r < 4; r++) acc[mt][nt][r] = 0.0f;

    int aRow0 = tid >> 2,           aColc0 = tid & 3;
    int aRow1 = (tid + 256) >> 2,   aColc1 = (tid + 256) & 3;
    int bRow0 = tid >> 5,           bCol0 = (tid & 31) << 2;
    int bRow1 = (tid + 256) >> 5;

    int NT = Ktot / BK;

    auto issue = [&](int kt, int buf) {
        int k0 = kt * BK;
        {
            int kk = k0 + aColc0 * 4;
            const float* src = (kk < K1) ? (A  + (size_t)(rowBase + aRow0) * K1 + kk)
                                         : (A2 + (size_t)(rowBase + aRow0) * K2 + (kk - K1));
            cp16(&As[buf][aRow0][aColc0 * 4], src);
        }
        {
            int kk = k0 + aColc1 * 4;
            const float* src = (kk < K1) ? (A  + (size_t)(rowBase + aRow1) * K1 + kk)
                                         : (A2 + (size_t)(rowBase + aRow1) * K2 + (kk - K1));
            cp16(&As[buf][aRow1][aColc1 * 4], src);
        }
        cp16(&Bs[buf][bRow0][bCol0], B + (size_t)(k0 + bRow0) * N + colBase + bCol0);
        cp16(&Bs[buf][bRow1][bCol0], B + (size_t)(k0 + bRow1) * N + colBase + bCol0);
    };

    issue(0, 0);
    asm volatile("cp.async.commit_group;\n");

    int buf = 0;
    for (int kt = 0; kt < NT; kt++) {
        if (kt + 1 < NT) {
            issue(kt + 1, buf ^ 1);
            asm volatile("cp.async.commit_group;\n");
            asm volatile("cp.async.wait_group 1;\n");
        } else {
            asm volatile("cp.async.wait_group 0;\n");
        }
        __syncthreads();

#pragma unroll
        for (int ks = 0; ks < 2; ks++) {
            int kb = ks * 8;
            uint32_t af[2][4];
#pragma unroll
            for (int mt = 0; mt < 2; mt++) {
                int m = wm0 + mt * 16;
                af[mt][0] = __float_as_uint(As[buf][m + g    ][kb + q    ]);
                af[mt][1] = __float_as_uint(As[buf][m + g + 8][kb + q    ]);
                af[mt][2] = __float_as_uint(As[buf][m + g    ][kb + q + 4]);
                af[mt][3] = __float_as_uint(As[buf][m + g + 8][kb + q + 4]);
            }
            uint32_t bf[8][2];
#pragma unroll
            for (int nt = 0; nt < 8; nt++) {
                int n = wn0 + nt * 8 + g;
                bf[nt][0] = __float_as_uint(Bs[buf][kb + q    ][n]);
                bf[nt][1] = __float_as_uint(Bs[buf][kb + q + 4][n]);
            }
#pragma unroll
            for (int mt = 0; mt < 2; mt++)
#pragma unroll
                for (int nt = 0; nt < 8; nt++) {
                    asm volatile(
                        "mma.sync.aligned.m16n8k8.row.col.f32.tf32.tf32.f32 "
                        "{%0,%1,%2,%3}, {%4,%5,%6,%7}, {%8,%9}, {%0,%1,%2,%3};\n"
                        : "+f"(acc[mt][nt][0]), "+f"(acc[mt][nt][1]),
                          "+f"(acc[mt][nt][2]), "+f"(acc[mt][nt][3])
                        : "r"(af[mt][0]), "r"(af[mt][1]), "r"(af[mt][2]), "r"(af[mt][3]),
                          "r"(bf[nt][0]), "r"(bf[nt][1]));
                }
        }
        buf ^= 1;
        __syncthreads();
    }

#pragma unroll
    for (int mt = 0; mt < 2; mt++) {
        int row = rowBase + wm0 + mt * 16 + g;
#pragma unroll
        for (int nt = 0; nt < 8; nt++) {
            int col = colBase + wn0 + nt * 8 + 2 * q;
            float v0 = acc[mt][nt][0], v1 = acc[mt][nt][1];
            float v2 = acc[mt][nt][2], v3 = acc[mt][nt][3];
            if (epi == EPI_ELU1) {
                v0 = (v0 > 0.f) ? v0 + 1.f : expf(v0);
                v1 = (v1 > 0.f) ? v1 + 1.f : expf(v1);
                v2 = (v2 > 0.f) ? v2 + 1.f : expf(v2);
                v3 = (v3 > 0.f) ? v3 + 1.f : expf(v3);
            } else if (epi == EPI_RELU_RND) {
                v0 = rnd_tf32(fmaxf(v0, 0.f)); v1 = rnd_tf32(fmaxf(v1, 0.f));
                v2 = rnd_tf32(fmaxf(v2, 0.f)); v3 = rnd_tf32(fmaxf(v3, 0.f));
            }
            *(float2*)(C + (size_t)row * N + col)       = make_float2(v0, v1);
            *(float2*)(C + (size_t)(row + 8) * N + col) = make_float2(v2, v3);
        }
    }
}

// ---------------- KV = sum_s K[s,d] * v[s,e], Ksum = sum_s K[s,d] per (n,h) ----------------
#define KV_CHUNKS 20
#define KV_SC (LL / KV_CHUNKS)
__global__ void kv_reduce_kernel(const float* __restrict__ Kb, const float* __restrict__ Vb,
                                 float* __restrict__ KV, float* __restrict__ KS) {
    int nh = blockIdx.x;
    int n = nh >> 3, h = nh & 7;
    int t = threadIdx.x;
    int d = t & 31;
    int eg = t >> 5;
    int s0 = blockIdx.y * KV_SC;
    float a0 = 0, a1 = 0, a2 = 0, a3 = 0, ks = 0;
    for (int s = s0; s < s0 + KV_SC; s++) {
        size_t base = ((size_t)(n * LL + s) * NHD + h) * HDD;
        float kd = Kb[base + d];
        float4 vv = *(const float4*)(Vb + base + eg * 4);
        a0 = fmaf(kd, vv.x, a0);
        a1 = fmaf(kd, vv.y, a1);
        a2 = fmaf(kd, vv.z, a2);
        a3 = fmaf(kd, vv.w, a3);
        ks += kd;
    }
    float* kvp = KV + ((size_t)nh * HDD + d) * HDD + eg * 4;
    atomicAdd(kvp + 0, a0);
    atomicAdd(kvp + 1, a1);
    atomicAdd(kvp + 2, a2);
    atomicAdd(kvp + 3, a3);
    if (eg == 0) atomicAdd(KS + nh * HDD + d, ks);
}

// ---------------- out[n,l,h,e] = (Q.KV[:,e]) / (Q.Ksum + eps), tf32-rounded ----------------
#define AT_CHUNKS 40
#define AT_RPB (LL / AT_CHUNKS)
__global__ void attn_apply_kernel(const float* __restrict__ Qb, const float* __restrict__ KV,
                                  const float* __restrict__ KS, float* __restrict__ O) {
    __shared__ float kvs[32][33];
    __shared__ float kss[32];
    int n = blockIdx.z, h = blockIdx.y;
    int nh = n * NHD + h;
    int t = threadIdx.x, lane = t & 31, w = t >> 5;
    for (int i = t; i < 1024; i += 256) kvs[i >> 5][i & 31] = KV[(size_t)nh * 1024 + i];
    if (t < 32) kss[t] = KS[nh * 32 + t];
    __syncthreads();
    int l0 = blockIdx.x * AT_RPB + w * (AT_RPB / 8);
    for (int r = 0; r < AT_RPB / 8; r++) {
        int l = l0 + r;
        size_t base = ((size_t)(n * LL + l) * NHD + h) * HDD;
        float qd = Qb[base + lane];
        float zs = qd * kss[lane];
#pragma unroll
        for (int o = 16; o; o >>= 1) zs += __shfl_xor_sync(0xffffffffu, zs, o);
        float z = 1.0f / (zs + 1e-6f);
        float acc = 0.0f;
#pragma unroll
        for (int d = 0; d < 32; d++) {
            float qv = __shfl_sync(0xffffffffu, qd, d);
            acc = fmaf(qv, kvs[d][lane], acc);
        }
        O[base + lane] = rnd_tf32(acc * z);
    }
}

// ---------------- LayerNorm over 256, output tf32-rounded (feeds GEMM) ----------------
__global__ void layernorm_kernel(float* __restrict__ X,
                                 const float* __restrict__ g, const float* __restrict__ b) {
    int row = blockIdx.x * 8 + (threadIdx.x >> 5);
    int lane = threadIdx.x & 31;
    size_t base = (size_t)row * CD;
    float v[8];
    float s = 0.0f;
#pragma unroll
    for (int i = 0; i < 8; i++) { v[i] = X[base + i * 32 + lane]; s += v[i]; }
#pragma unroll
    for (int o = 16; o; o >>= 1) s += __shfl_xor_sync(0xffffffffu, s, o);
    float mu = s * (1.0f / 256.0f);
    float q = 0.0f;
#pragma unroll
    for (int i = 0; i < 8; i++) { float d = v[i] - mu; q = fmaf(d, d, q); }
#pragma unroll
    for (int o = 16; o; o >>= 1) q += __shfl_xor_sync(0xffffffffu, q, o);
    float rs = rsqrtf(q * (1.0f / 256.0f) + 1e-5f);
#pragma unroll
    for (int i = 0; i < 8; i++)
        X[base + i * 32 + lane] =
            rnd_tf32((v[i] - mu) * rs * g[i * 32 + lane] + b[i * 32 + lane]);
}

// X += LayerNorm(Y); Xr = tf32(X)
__global__ void ln_residual_kernel(float* __restrict__ X, float* __restrict__ Xr,
                                   const float* __restrict__ Y,
                                   const float* __restrict__ g, const float* __restrict__ b) {
    int row = blockIdx.x * 8 + (threadIdx.x >> 5);
    int lane = threadIdx.x & 31;
    size_t base = (size_t)row * CD;
    float v[8];
    float s = 0.0f;
#pragma unroll
    for (int i = 0; i < 8; i++) { v[i] = Y[base + i * 32 + lane]; s += v[i]; }
#pragma unroll
    for (int o = 16; o; o >>= 1) s += __shfl_xor_sync(0xffffffffu, s, o);
    float mu = s * (1.0f / 256.0f);
    float q = 0.0f;
#pragma unroll
    for (int i = 0; i < 8; i++) { float d = v[i] - mu; q = fmaf(d, d, q); }
#pragma unroll
    for (int o = 16; o; o >>= 1) q += __shfl_xor_sync(0xffffffffu, q, o);
    float rs = rsqrtf(q * (1.0f / 256.0f) + 1e-5f);
#pragma unroll
    for (int i = 0; i < 8; i++) {
        size_t o = base + i * 32 + lane;
        float nx = X[o] + (v[i] - mu) * rs * g[i * 32 + lane] + b[i * 32 + lane];
        X[o] = nx;
        Xr[o] = rnd_tf32(nx);
    }
}

// ---------------- launch ----------------
extern "C" void kernel_launch(void* const* d_in, const int* in_sizes, int n_in,
                              void* d_out, int out_size) {
    const float* feat0 = (const float*)d_in[0];
    const float* feat1 = (const float*)d_in[1];
    const float* Wq = (const float*)d_in[2];
    const float* Wk = (const float*)d_in[3];
    const float* Wv = (const float*)d_in[4];
    const float* Wm = (const float*)d_in[5];
    const float* W1 = (const float*)d_in[6];
    const float* W2 = (const float*)d_in[7];
    const float* g1 = (const float*)d_in[8];
    const float* b1 = (const float*)d_in[9];
    const float* g2 = (const float*)d_in[10];
    const float* b2 = (const float*)d_in[11];

    float *F0, *F0r, *F1, *Qb, *Kb, *Vb, *KV, *KS, *PE;
    float *wQ, *wK, *wV, *wM, *w1p, *w2p;
    cudaGetSymbolAddress((void**)&F0,  g_F0);
    cudaGetSymbolAddress((void**)&F0r, g_F0r);
    cudaGetSymbolAddress((void**)&F1,  g_F1);
    cudaGetSymbolAddress((void**)&Qb,  g_Q);
    cudaGetSymbolAddress((void**)&Kb,  g_K);
    cudaGetSymbolAddress((void**)&Vb,  g_V);
    cudaGetSymbolAddress((void**)&KV,  g_KV);
    cudaGetSymbolAddress((void**)&KS,  g_KS);
    cudaGetSymbolAddress((void**)&PE,  g_PE);
    cudaGetSymbolAddress((void**)&wQ,  g_Wq);
    cudaGetSymbolAddress((void**)&wK,  g_Wk);
    cudaGetSymbolAddress((void**)&wV,  g_Wv);
    cudaGetSymbolAddress((void**)&wM,  g_Wm);
    cudaGetSymbolAddress((void**)&w1p, g_W1);
    cudaGetSymbolAddress((void**)&w2p, g_W2);

    weight_prep_kernel<<<(2 * 2 * CD * CD + 255) / 256, 256>>>(Wq, Wk, Wv, Wm, W1, W2);
    pe_precompute_kernel<<<(CD * LL + 255) / 256, 256>>>(PE);

    dim3 tb(32, 8);
    dim3 tg(LL / 32, CD / 32, NB);
    build_pe_kernel<<<tg, tb>>>(feat0, PE, F0, F0r);
    build_pe_kernel<<<tg, tb>>>(feat1, PE, nullptr, F1);   // F1 rounded only

    dim3 gg(CD / 128, MR / 128);

    for (int i = 0; i < 2; i++) {
        const float* wq = wQ + (size_t)i * CD * CD;
        const float* wk = wK + (size_t)i * CD * CD;
        const float* wv = wV + (size_t)i * CD * CD;
        const float* wm = wM + (size_t)i * CD * CD;
        const float* w1 = w1p + (size_t)i * 2 * CD * CD;
        const float* w2 = w2p + (size_t)i * CD * CD;

        // projections (elu+1 fused into q,k; outputs feed fp32 kernels, no rounding)
        tgemm_kernel<<<gg, 256>>>(F0r, F0r, wq, Qb, MR, CD, CD, CD, EPI_ELU1);
        tgemm_kernel<<<gg, 256>>>(F1,  F1,  wk, Kb, MR, CD, CD, CD, EPI_ELU1);
        tgemm_kernel<<<gg, 256>>>(F1,  F1,  wv, Vb, MR, CD, CD, CD, EPI_NONE);

        // KV / Ksum reduction
        cudaMemsetAsync(KV, 0, sizeof(float) * NB * NHD * HDD * HDD, 0);
        cudaMemsetAsync(KS, 0, sizeof(float) * NB * NHD * HDD, 0);
        kv_reduce_kernel<<<dim3(NB * NHD, KV_CHUNKS), 256>>>(Kb, Vb, KV, KS);

        // attention apply -> Kb (rounded: feeds merge GEMM)
        attn_apply_kernel<<<dim3(AT_CHUNKS, NHD, NB), 256>>>(Qb, KV, KS, Kb);

        // merge projection -> Vb, LN1 in place (rounded: feeds FFN1)
        tgemm_kernel<<<gg, 256>>>(Kb, Kb, wm, Vb, MR, CD, CD, CD, EPI_NONE);
        layernorm_kernel<<<MR / 8, 256>>>(Vb, g1 + i * CD, b1 + i * CD);

        // FFN: relu([x|msg] @ W1) rounded -> Qb; @ W2 -> Kb; x += LN2(Kb)
        tgemm_kernel<<<gg, 256>>>(F0r, Vb, w1, Qb, MR, 2 * CD, CD, CD, EPI_RELU_RND);
        tgemm_kernel<<<gg, 256>>>(Qb, Qb, w2, Kb, MR, CD, CD, CD, EPI_NONE);
        ln_residual_kernel<<<MR / 8, 256>>>(F0, F0r, Kb, g2 + i * CD, b2 + i * CD);
    }

    unbuild_kernel<<<tg, tb>>>(F0, (float*)d_out);
}